// round 12
// baseline (speedup 1.0000x reference)
#include <cuda_runtime.h>
#include <cuda_fp16.h>
#include <cstdint>

// Problem constants
#define NA   2048           // atoms
#define ND   64             // depth
#define NF   12             // filters
#define KTOT (NA * NF)      // 24576, GEMM K
#define DP2  (ND + 2)       // 66
#define FSTR (NF * DP2)     // 792

// GEMM tiling
#define MTILE   128
#define SPLITS  8
#define KCHUNK  (KTOT / SPLITS)   // 3072
#define KB      64                // k per smem stage
#define NSTAGES (KCHUNK / KB)     // 48
#define SPAD    72                // row stride in halves (144B; ldmatrix conflict-free)
#define PIPE    4                 // cp.async pipeline depth
#define GEMM_SMEM (PIPE * (MTILE + ND) * SPAD * 2)   // 110592 B dynamic smem
#define GT      512               // gemm threads (16 warps, 4x4)

// ---------------- device scratch (static module allocations, no runtime alloc) ---------
__device__ __align__(16) __half g_connH[(size_t)NA * KTOT];     // ~100.7 MB fp16 conn
__device__ __align__(16) __half g_WT[(size_t)ND * KTOT];        // W fp16 scaled [o][k]
__device__ __align__(16) float  g_Ft[2 * NF * ND * ND];         // filters transposed [L][f][d][o]
__device__ __align__(16) float  g_bias[2][NA * ND];
__device__ __align__(16) float  g_act[NA * ND];
__device__ __align__(16) float  g_part[(NA / MTILE) * SPLITS * MTILE * ND];
__device__ unsigned int g_amax_bits[5];
__device__ float g_B[2];

// ---------------- helpers ----------------
__device__ __forceinline__ uint32_t smem_u32(const void* p) {
    return (uint32_t)__cvta_generic_to_shared(p);
}

__device__ __forceinline__ void ldmx4(uint32_t* r, uint32_t addr) {
    asm volatile("ldmatrix.sync.aligned.m8n8.x4.shared.b16 {%0,%1,%2,%3}, [%4];"
                 : "=r"(r[0]), "=r"(r[1]), "=r"(r[2]), "=r"(r[3]) : "r"(addr));
}

__device__ __forceinline__ void mma16816(float* c, const uint32_t* a, uint32_t b0, uint32_t b1) {
    asm volatile(
        "mma.sync.aligned.m16n8k16.row.col.f32.f16.f16.f32 "
        "{%0,%1,%2,%3}, {%4,%5,%6,%7}, {%8,%9}, {%0,%1,%2,%3};"
        : "+f"(c[0]), "+f"(c[1]), "+f"(c[2]), "+f"(c[3])
        : "r"(a[0]), "r"(a[1]), "r"(a[2]), "r"(a[3]), "r"(b0), "r"(b1));
}

// scale = 2^(14-e) if bound >= 2^14 else 1 (power of 2 -> exact)
__device__ __forceinline__ float w_scale(int c, int L) {
    float bound = __uint_as_float(g_amax_bits[c]) * g_B[L];
    int e; frexpf(bound, &e);
    return (e > 14) ? ldexpf(1.f, 14 - e) : 1.f;
}
__device__ __forceinline__ float w_invscale(int c, int L) {
    float bound = __uint_as_float(g_amax_bits[c]) * g_B[L];
    int e; frexpf(bound, &e);
    return (e > 14) ? ldexpf(1.f, e - 14) : 1.f;
}

// ---------------- kernel: fp32 conn -> fp16, 2 block-strided float4 per thread --------
// __ldcs: stream fp32 source through L2 (evict-first) so fp16 connH stays resident
__global__ void k_conv_half(const float4* __restrict__ src, int n4) {
    int base = blockIdx.x * 512 + threadIdx.x;
    uint2* dst = reinterpret_cast<uint2*>(g_connH);
#pragma unroll
    for (int j = 0; j < 2; j++) {
        int i = base + j * 256;
        if (i < n4) {
            float4 v = __ldcs(&src[i]);
            __half2 h0 = __floats2half2_rn(v.x, v.y);
            __half2 h1 = __floats2half2_rn(v.z, v.w);
            uint2 u;
            u.x = *reinterpret_cast<uint32_t*>(&h0);
            u.y = *reinterpret_cast<uint32_t*>(&h1);
            dst[i] = u;
        }
    }
}

// ---------------- kernel prepA: filter transpose + bias ----------------
// blocks [0,384): transpose Ft; [384,896): bias
__global__ void k_prepA(const float* __restrict__ bond,
                        const float* __restrict__ f0, const float* __restrict__ f1) {
    int b = blockIdx.x;
    int t = threadIdx.x;
    if (b < 384) {
        int idx = b * 256 + t;                 // < 98304 = 2*12*64*64
        int o = idx & 63;
        int d = (idx >> 6) & 63;
        int f = (idx >> 12) % NF;
        int L = idx / (NF * ND * ND);
        const float* src = L ? f1 : f0;
        g_Ft[idx] = src[o * FSTR + f * DP2 + d];
    } else {
        int i = (b - 384) * 256 + t;           // < 131072 = 2048*64
        int a = i >> 6, o = i & 63;
        float bb[NF * 2];
#pragma unroll
        for (int j = 0; j < NF * 2; j++) bb[j] = bond[a * NF * 2 + j];
#pragma unroll
        for (int L = 0; L < 2; L++) {
            const float* flt = L ? f1 : f0;
            float s = 0.f;
#pragma unroll
            for (int f = 0; f < NF; f++) {
                s += bb[f * 2 + 0] * flt[o * FSTR + f * DP2 + ND + 0];
                s += bb[f * 2 + 1] * flt[o * FSTR + f * DP2 + ND + 1];
            }
            g_bias[L][i] = s;
        }
    }
}

// ---------------- kernel prepB: filter colsum bounds + amax(x) ----------------
// blocks 0,1 -> g_B[L]; block 2 -> amax(x) into slot 0, zero slots 1..4
__global__ void k_prepB(const float* __restrict__ x,
                        const float* __restrict__ f0, const float* __restrict__ f1) {
    __shared__ float sred[256];
    int b = blockIdx.x;
    int t = threadIdx.x;
    if (b < 2) {
        const float* flt = b ? f1 : f0;
        float mx = 0.f;
        for (int i = t; i < ND * NF; i += 256) {
            int o = i / NF, f = i - o * NF;
            const float* p = flt + o * FSTR + f * DP2;
            float s = 0.f;
#pragma unroll
            for (int d = 0; d < ND; d++) s += fabsf(p[d]);
            mx = fmaxf(mx, s);
        }
        sred[t] = mx;
        __syncthreads();
        for (int off = 128; off; off >>= 1) {
            if (t < off) sred[t] = fmaxf(sred[t], sred[t + off]);
            __syncthreads();
        }
        if (t == 0) g_B[b] = sred[0];
    } else {
        float mx = 0.f;
        for (int i = t; i < NA * ND; i += 256) mx = fmaxf(mx, fabsf(x[i]));
        sred[t] = mx;
        __syncthreads();
        for (int off = 128; off; off >>= 1) {
            if (t < off) sred[t] = fmaxf(sred[t], sred[t + off]);
            __syncthreads();
        }
        if (t == 0) {
            g_amax_bits[0] = __float_as_uint(sred[0]);
            g_amax_bits[1] = 0u; g_amax_bits[2] = 0u;
            g_amax_bits[3] = 0u; g_amax_bits[4] = 0u;
        }
    }
}

// ---------------- kernel: WT[o][k] = scale * sum_d act[n,d] * Ft[L][f][d][o] ----------
__global__ void k_W(const float* __restrict__ xin, int c, int L) {
    __shared__ float sF[NF * ND];
    int o = blockIdx.x;
    int t = threadIdx.x;
    const float* act = (c == 0) ? xin : g_act;
    float sc = w_scale(c, L);
    for (int i = t; i < NF * ND; i += 256)
        sF[i] = g_Ft[(L * NF * ND + i) * ND + o];
    __syncthreads();
    int kbase = blockIdx.y * 1024;
#pragma unroll
    for (int j = 0; j < 4; j++) {
        int k = kbase + j * 256 + t;
        int n = k / NF;
        int f = k - n * NF;
        const float4* ar = reinterpret_cast<const float4*>(act + n * ND);
        const float* fr = &sF[f * ND];
        float s = 0.f;
#pragma unroll
        for (int d4 = 0; d4 < 16; d4++) {
            float4 v = ar[d4];
            s += v.x * fr[d4 * 4 + 0] + v.y * fr[d4 * 4 + 1]
               + v.z * fr[d4 * 4 + 2] + v.w * fr[d4 * 4 + 3];
        }
        g_WT[(size_t)o * KTOT + k] = __float2half_rn(s * sc);
    }
}

// ---------------- split-K GEMM: 512 threads = 16 warps (4x4), warp tile 32x16 ---------
// grid (16 m-tiles, 8 splits); PIPE=4 x KB=64 cp.async pipeline
__global__ __launch_bounds__(GT, 1) void k_gemm() {
    extern __shared__ __align__(16) __half dyn[];
    __half* sAb = dyn;                          // [PIPE][MTILE][SPAD]
    __half* sBb = dyn + PIPE * MTILE * SPAD;    // [PIPE][ND][SPAD]

    int t = threadIdx.x;
    int mt = blockIdx.x, sp = blockIdx.y;
    int K0 = sp * KCHUNK;
    int lane = t & 31, w = t >> 5;
    int wm = w & 3, wn = w >> 2;                // 4x4 warp grid

    float acc[2][2][4];
#pragma unroll
    for (int i = 0; i < 2; i++)
#pragma unroll
        for (int j = 0; j < 2; j++)
#pragma unroll
            for (int q = 0; q < 4; q++) acc[i][j][q] = 0.f;

    // stage = 64 halves/row: A 128 rows (1024 x 16B chunks), B 64 rows (512 chunks)
    auto LOAD = [&](int buf, int kb) {
        __half* A = sAb + buf * MTILE * SPAD;
        __half* B = sBb + buf * ND * SPAD;
#pragma unroll
        for (int j = 0; j < 2; j++) {
            int idx = j * GT + t;
            int row = idx >> 3, c16 = idx & 7;
            const __half* src = g_connH + (size_t)(mt * MTILE + row) * KTOT + K0 + kb + c16 * 8;
            uint32_t dst = smem_u32(A + row * SPAD + c16 * 8);
            asm volatile("cp.async.cg.shared.global [%0], [%1], 16;" :: "r"(dst), "l"(src));
        }
        {
            int row = t >> 3, c16 = t & 7;
            const __half* src = g_WT + (size_t)row * KTOT + K0 + kb + c16 * 8;
            uint32_t dst = smem_u32(B + row * SPAD + c16 * 8);
            asm volatile("cp.async.cg.shared.global [%0], [%1], 16;" :: "r"(dst), "l"(src));
        }
        asm volatile("cp.async.commit_group;");
    };

    int ar = (lane & 7) + ((lane >> 3) & 1) * 8;   // A-fragment row within m16
    int asel = (lane >> 4) * 8;                    // A-fragment k-half
    int br = (lane & 7) + (lane >> 4) * 8;         // B n-row select (0..15)
    int bsel = ((lane >> 3) & 1) * 8;              // B k-half

    auto COMPUTE = [&](int buf) {
        __half* A = sAb + buf * MTILE * SPAD;
        __half* B = sBb + buf * ND * SPAD;
#pragma unroll
        for (int kk = 0; kk < KB; kk += 16) {
            uint32_t a[2][4], b[4];
#pragma unroll
            for (int mi = 0; mi < 2; mi++) {
                uint32_t ad = smem_u32(A + (wm * 32 + mi * 16 + ar) * SPAD + kk + asel);
                ldmx4(a[mi], ad);
            }
            {
                uint32_t bd = smem_u32(B + (wn * 16 + br) * SPAD + kk + bsel);
                ldmx4(b, bd);   // n16 x k16 -> {n8#0 k0, n8#0 k1, n8#1 k0, n8#1 k1}
            }
#pragma unroll
            for (int mi = 0; mi < 2; mi++)
#pragma unroll
                for (int nt = 0; nt < 2; nt++)
                    mma16816(acc[mi][nt], a[mi], b[nt * 2], b[nt * 2 + 1]);
        }
    };

    // prologue: PIPE-1 stages in flight
#pragma unroll
    for (int s = 0; s < PIPE - 1; s++) LOAD(s, s * KB);

    int buf = 0;
    for (int s = 0; s < NSTAGES; s++) {
        asm volatile("cp.async.wait_group %0;" :: "n"(PIPE - 2));
        __syncthreads();
        int nxt = s + PIPE - 1;
        if (nxt < NSTAGES) {
            int wb = buf + (PIPE - 1); if (wb >= PIPE) wb -= PIPE;
            LOAD(wb, nxt * KB);
        } else {
            asm volatile("cp.async.commit_group;");   // keep group accounting invariant
        }
        COMPUTE(buf);
        if (++buf == PIPE) buf = 0;
    }

    // epilogue: write partials (unique writer per element -> deterministic)
    int g = lane >> 2, q = lane & 3;
    size_t pbase = (size_t)(mt * SPLITS + sp) * MTILE * ND;
#pragma unroll
    for (int mi = 0; mi < 2; mi++)
#pragma unroll
        for (int nt = 0; nt < 2; nt++) {
            int lrow = wm * 32 + mi * 16 + g;
            int col = wn * 16 + nt * 8 + q * 2;
            float2* p0 = reinterpret_cast<float2*>(&g_part[pbase + (size_t)lrow * ND + col]);
            *p0 = make_float2(acc[mi][nt][0], acc[mi][nt][1]);
            float2* p1 = reinterpret_cast<float2*>(&g_part[pbase + (size_t)(lrow + 8) * ND + col]);
            *p1 = make_float2(acc[mi][nt][2], acc[mi][nt][3]);
        }
}

// ---------------- split-K reduce * invscale + bias (+x) + ReLU + amax ----------------
__global__ void k_reduce(int c, int L, int addX, int writeOut,
                         const float* __restrict__ x, float* __restrict__ dout) {
    __shared__ float smax[8];
    int t = threadIdx.x;
    int idx = blockIdx.x * 256 + t;   // a*64 + o
    int a = idx >> 6;
    int o = idx & 63;
    int mtl = a >> 7;
    int lr = a & 127;
    float inv = w_invscale(c, L);
    float s = 0.f;
#pragma unroll
    for (int sp = 0; sp < SPLITS; sp++)
        s += g_part[(size_t)(mtl * SPLITS + sp) * MTILE * ND + (size_t)lr * ND + o];
    float v = s * inv + g_bias[L][idx];
    if (addX) v += x[idx];
    v = fmaxf(v, 0.f);
    g_act[idx] = v;
    if (writeOut) dout[idx] = v;
    float mx = v;
#pragma unroll
    for (int off = 16; off; off >>= 1)
        mx = fmaxf(mx, __shfl_xor_sync(0xffffffffu, mx, off));
    if ((t & 31) == 0) smax[t >> 5] = mx;
    __syncthreads();
    if (t == 0) {
#pragma unroll
        for (int ww = 1; ww < 8; ww++) mx = fmaxf(mx, smax[ww]);
        atomicMax(&g_amax_bits[c + 1], __float_as_uint(mx));
    }
}

// ---------------- launcher ----------------
extern "C" void kernel_launch(void* const* d_in, const int* in_sizes, int n_in,
                              void* d_out, int out_size) {
    const float* x    = (const float*)d_in[0];   // (2048, 64)
    const float* conn = (const float*)d_in[1];   // (2048, 2048, 12)
    const float* bond = (const float*)d_in[2];   // (2048, 12, 2)
    const float* f0   = (const float*)d_in[3];   // (64, 12, 66)
    const float* f1   = (const float*)d_in[4];   // (64, 12, 66)
    float* out = (float*)d_out;                  // (2048, 64)

    cudaFuncSetAttribute(k_gemm, cudaFuncAttributeMaxDynamicSharedMemorySize, GEMM_SMEM);

    int n4 = (NA * NA * NF) / 4;                 // 12,582,912

    // Order chosen so launch #4 (= ncu capture slot) is k_conv_half.
    // Dependencies: prepB before k_W (scale); conv_half before k_gemm.
    k_prepA<<<896, 256>>>(bond, f0, f1);                        // 1
    k_prepB<<<3, 256>>>(x, f0, f1);                             // 2
    k_W<<<dim3(64, 24), 256>>>(x, 0, 0);                        // 3 (c=0)
    k_conv_half<<<(n4 + 511) / 512, 256>>>((const float4*)conn, n4);  // 4 <- captured
    k_gemm<<<dim3(NA / MTILE, SPLITS), GT, GEMM_SMEM>>>();      // 5 (c=0)
    k_reduce<<<(NA * ND) / 256, 256>>>(0, 0, 0, 0, x, out);     // 6

    for (int c = 1; c < 4; c++) {
        int L = c >> 1;
        k_W<<<dim3(64, 24), 256>>>(x, c, L);
        k_gemm<<<dim3(NA / MTILE, SPLITS), GT, GEMM_SMEM>>>();
        k_reduce<<<(NA * ND) / 256, 256>>>(c, L, c & 1, (c == 3) ? 1 : 0, x, out);
    }
}

// round 15
// speedup vs baseline: 2.2110x; 2.2110x over previous
#include <cuda_runtime.h>
#include <cuda_fp16.h>
#include <cstdint>

// Problem constants
#define NA   2048           // atoms
#define ND   64             // depth
#define NF   12             // filters
#define KTOT (NA * NF)      // 24576, GEMM K
#define DP2  (ND + 2)       // 66
#define FSTR (NF * DP2)     // 792

// GEMM tiling
#define MTILE   128
#define SPLITS  8
#define KCHUNK  (KTOT / SPLITS)   // 3072
#define KB      64                // k per smem stage
#define NSTAGES (KCHUNK / KB)     // 48
#define SPAD    72                // row stride in halves (144B; ldmatrix conflict-free)
#define PIPE    4                 // cp.async pipeline depth
#define GEMM_SMEM (PIPE * (MTILE + ND) * SPAD * 2)   // 110592 B dynamic smem
#define GT      512               // gemm threads (16 warps, 4x4)

// ---------------- device scratch (static module allocations, no runtime alloc) ---------
__device__ __align__(16) __half g_connH[(size_t)NA * KTOT];     // ~100.7 MB fp16 conn
__device__ __align__(16) __half g_WT[(size_t)ND * KTOT];        // W fp16 scaled [o][k]
__device__ __align__(16) float  g_Ft[2 * NF * ND * ND];         // filters transposed [L][f][d][o]
__device__ __align__(16) float  g_bias[2][NA * ND];
__device__ __align__(16) float  g_act[NA * ND];
__device__ __align__(16) float  g_part[(NA / MTILE) * SPLITS * MTILE * ND];
__device__ unsigned int g_amax_bits[5];
__device__ float g_B[2];

// ---------------- helpers ----------------
__device__ __forceinline__ uint32_t smem_u32(const void* p) {
    return (uint32_t)__cvta_generic_to_shared(p);
}

__device__ __forceinline__ void ldmx4(uint32_t* r, uint32_t addr) {
    asm volatile("ldmatrix.sync.aligned.m8n8.x4.shared.b16 {%0,%1,%2,%3}, [%4];"
                 : "=r"(r[0]), "=r"(r[1]), "=r"(r[2]), "=r"(r[3]) : "r"(addr));
}

__device__ __forceinline__ void mma16816(float* c, const uint32_t* a, uint32_t b0, uint32_t b1) {
    asm volatile(
        "mma.sync.aligned.m16n8k16.row.col.f32.f16.f16.f32 "
        "{%0,%1,%2,%3}, {%4,%5,%6,%7}, {%8,%9}, {%0,%1,%2,%3};"
        : "+f"(c[0]), "+f"(c[1]), "+f"(c[2]), "+f"(c[3])
        : "r"(a[0]), "r"(a[1]), "r"(a[2]), "r"(a[3]), "r"(b0), "r"(b1));
}

// scale = 2^(14-e) if bound >= 2^14 else 1 (power of 2 -> exact)
__device__ __forceinline__ float w_scale(int c, int L) {
    float bound = __uint_as_float(g_amax_bits[c]) * g_B[L];
    int e; frexpf(bound, &e);
    return (e > 14) ? ldexpf(1.f, 14 - e) : 1.f;
}
__device__ __forceinline__ float w_invscale(int c, int L) {
    float bound = __uint_as_float(g_amax_bits[c]) * g_B[L];
    int e; frexpf(bound, &e);
    return (e > 14) ? ldexpf(1.f, e - 14) : 1.f;
}

// ---------------- kernel: fp32 conn -> fp16, 2 block-strided float4 per thread --------
__global__ void k_conv_half(const float4* __restrict__ src, int n4) {
    int base = blockIdx.x * 512 + threadIdx.x;
    uint2* dst = reinterpret_cast<uint2*>(g_connH);
#pragma unroll
    for (int j = 0; j < 2; j++) {
        int i = base + j * 256;
        if (i < n4) {
            float4 v = __ldcs(&src[i]);
            __half2 h0 = __floats2half2_rn(v.x, v.y);
            __half2 h1 = __floats2half2_rn(v.z, v.w);
            uint2 u;
            u.x = *reinterpret_cast<uint32_t*>(&h0);
            u.y = *reinterpret_cast<uint32_t*>(&h1);
            dst[i] = u;
        }
    }
}

// ---------------- kernel prepB: Ft transpose + filter colsum bounds + amax(x) ----------
// blocks 0,1 -> g_B[L]; block 2 -> amax(x) + zero slots; blocks 3..386 -> Ft transpose
__global__ void k_prepB(const float* __restrict__ x,
                        const float* __restrict__ f0, const float* __restrict__ f1) {
    __shared__ float sred[256];
    int b = blockIdx.x;
    int t = threadIdx.x;
    if (b >= 3) {
        int idx = (b - 3) * 256 + t;           // < 98304 = 2*12*64*64
        int o = idx & 63;
        int d = (idx >> 6) & 63;
        int f = (idx >> 12) % NF;
        int L = idx / (NF * ND * ND);
        const float* src = L ? f1 : f0;
        g_Ft[idx] = src[o * FSTR + f * DP2 + d];
        return;
    }
    if (b < 2) {
        const float* flt = b ? f1 : f0;
        float mx = 0.f;
        for (int i = t; i < ND * NF; i += 256) {
            int o = i / NF, f = i - o * NF;
            const float* p = flt + o * FSTR + f * DP2;
            float s = 0.f;
#pragma unroll
            for (int d = 0; d < ND; d++) s += fabsf(p[d]);
            mx = fmaxf(mx, s);
        }
        sred[t] = mx;
        __syncthreads();
        for (int off = 128; off; off >>= 1) {
            if (t < off) sred[t] = fmaxf(sred[t], sred[t + off]);
            __syncthreads();
        }
        if (t == 0) g_B[b] = sred[0];
    } else {
        float mx = 0.f;
        for (int i = t; i < NA * ND; i += 256) mx = fmaxf(mx, fabsf(x[i]));
        sred[t] = mx;
        __syncthreads();
        for (int off = 128; off; off >>= 1) {
            if (t < off) sred[t] = fmaxf(sred[t], sred[t + off]);
            __syncthreads();
        }
        if (t == 0) {
            g_amax_bits[0] = __float_as_uint(sred[0]);
            g_amax_bits[1] = 0u; g_amax_bits[2] = 0u;
            g_amax_bits[3] = 0u; g_amax_bits[4] = 0u;
        }
    }
}

// ---------------- kernel prepA: bias[L][a][o] = sum_{f,j} bond[a,f,j]*filt[o,f,D+j] ----
__global__ void k_prepA(const float* __restrict__ bond,
                        const float* __restrict__ f0, const float* __restrict__ f1) {
    int i = blockIdx.x * 256 + threadIdx.x;    // < 131072 = 2048*64
    int a = i >> 6, o = i & 63;
    float bb[NF * 2];
#pragma unroll
    for (int j = 0; j < NF * 2; j++) bb[j] = bond[a * NF * 2 + j];
#pragma unroll
    for (int L = 0; L < 2; L++) {
        const float* flt = L ? f1 : f0;
        float s = 0.f;
#pragma unroll
        for (int f = 0; f < NF; f++) {
            s += bb[f * 2 + 0] * flt[o * FSTR + f * DP2 + ND + 0];
            s += bb[f * 2 + 1] * flt[o * FSTR + f * DP2 + ND + 1];
        }
        g_bias[L][i] = s;
    }
}

// ---------------- kernel k_W v2: one thread = one atom row, 12 accumulators ------------
// grid (64 o, 8 n-chunks), 256 threads. Row held in 64 regs; sF broadcast from smem;
// output staged in smem -> coalesced uint32 writes. 12x fewer global loads than v1.
__global__ void k_W(const float* __restrict__ xin, int c, int L) {
    __shared__ float sF[NF * ND];                 // Ft column for this o: [f][d]
    __shared__ __align__(16) __half sW[256 * NF]; // 6 KB staging
    int o = blockIdx.x;
    int t = threadIdx.x;
    const float* act = (c == 0) ? xin : g_act;
    float sc = w_scale(c, L);
    for (int i = t; i < NF * ND; i += 256)
        sF[i] = g_Ft[(L * NF * ND + i) * ND + o];
    __syncthreads();

    int n = blockIdx.y * 256 + t;
    float4 row[16];
    const float4* ar = reinterpret_cast<const float4*>(act + n * ND);
#pragma unroll
    for (int i = 0; i < 16; i++) row[i] = ar[i];

#pragma unroll
    for (int f = 0; f < NF; f++) {
        const float4* fr = reinterpret_cast<const float4*>(&sF[f * ND]);
        float s = 0.f;
#pragma unroll
        for (int i = 0; i < 16; i++) {
            float4 v = row[i];
            float4 wv = fr[i];
            s += v.x * wv.x + v.y * wv.y + v.z * wv.z + v.w * wv.w;
        }
        sW[t * NF + f] = __float2half_rn(s * sc);
    }
    __syncthreads();

    // coalesced write: 3072 halves = 1536 uint32, k = chunk*3072 + t*12 + f
    const uint32_t* sw32 = reinterpret_cast<const uint32_t*>(sW);
    uint32_t* dst = reinterpret_cast<uint32_t*>(
        g_WT + (size_t)o * KTOT + (size_t)blockIdx.y * (256 * NF));
#pragma unroll
    for (int i = 0; i < 6; i++)
        dst[i * 256 + t] = sw32[i * 256 + t];
}

// ---------------- split-K GEMM: 512 threads = 16 warps (4x4), warp tile 32x16 ---------
__global__ __launch_bounds__(GT, 1) void k_gemm() {
    extern __shared__ __align__(16) __half dyn[];
    __half* sAb = dyn;                          // [PIPE][MTILE][SPAD]
    __half* sBb = dyn + PIPE * MTILE * SPAD;    // [PIPE][ND][SPAD]

    int t = threadIdx.x;
    int mt = blockIdx.x, sp = blockIdx.y;
    int K0 = sp * KCHUNK;
    int lane = t & 31, w = t >> 5;
    int wm = w & 3, wn = w >> 2;                // 4x4 warp grid

    float acc[2][2][4];
#pragma unroll
    for (int i = 0; i < 2; i++)
#pragma unroll
        for (int j = 0; j < 2; j++)
#pragma unroll
            for (int q = 0; q < 4; q++) acc[i][j][q] = 0.f;

    auto LOAD = [&](int buf, int kb) {
        __half* A = sAb + buf * MTILE * SPAD;
        __half* B = sBb + buf * ND * SPAD;
#pragma unroll
        for (int j = 0; j < 2; j++) {
            int idx = j * GT + t;
            int row = idx >> 3, c16 = idx & 7;
            const __half* src = g_connH + (size_t)(mt * MTILE + row) * KTOT + K0 + kb + c16 * 8;
            uint32_t dst = smem_u32(A + row * SPAD + c16 * 8);
            asm volatile("cp.async.cg.shared.global [%0], [%1], 16;" :: "r"(dst), "l"(src));
        }
        {
            int row = t >> 3, c16 = t & 7;
            const __half* src = g_WT + (size_t)row * KTOT + K0 + kb + c16 * 8;
            uint32_t dst = smem_u32(B + row * SPAD + c16 * 8);
            asm volatile("cp.async.cg.shared.global [%0], [%1], 16;" :: "r"(dst), "l"(src));
        }
        asm volatile("cp.async.commit_group;");
    };

    int ar = (lane & 7) + ((lane >> 3) & 1) * 8;   // A-fragment row within m16
    int asel = (lane >> 4) * 8;                    // A-fragment k-half
    int br = (lane & 7) + (lane >> 4) * 8;         // B n-row select (0..15)
    int bsel = ((lane >> 3) & 1) * 8;              // B k-half

    auto COMPUTE = [&](int buf) {
        __half* A = sAb + buf * MTILE * SPAD;
        __half* B = sBb + buf * ND * SPAD;
#pragma unroll
        for (int kk = 0; kk < KB; kk += 16) {
            uint32_t a[2][4], b[4];
#pragma unroll
            for (int mi = 0; mi < 2; mi++) {
                uint32_t ad = smem_u32(A + (wm * 32 + mi * 16 + ar) * SPAD + kk + asel);
                ldmx4(a[mi], ad);
            }
            {
                uint32_t bd = smem_u32(B + (wn * 16 + br) * SPAD + kk + bsel);
                ldmx4(b, bd);   // n16 x k16 -> {n8#0 k0, n8#0 k1, n8#1 k0, n8#1 k1}
            }
#pragma unroll
            for (int mi = 0; mi < 2; mi++)
#pragma unroll
                for (int nt = 0; nt < 2; nt++)
                    mma16816(acc[mi][nt], a[mi], b[nt * 2], b[nt * 2 + 1]);
        }
    };

#pragma unroll
    for (int s = 0; s < PIPE - 1; s++) LOAD(s, s * KB);

    int buf = 0;
    for (int s = 0; s < NSTAGES; s++) {
        asm volatile("cp.async.wait_group %0;" :: "n"(PIPE - 2));
        __syncthreads();
        int nxt = s + PIPE - 1;
        if (nxt < NSTAGES) {
            int wb = buf + (PIPE - 1); if (wb >= PIPE) wb -= PIPE;
            LOAD(wb, nxt * KB);
        } else {
            asm volatile("cp.async.commit_group;");
        }
        COMPUTE(buf);
        if (++buf == PIPE) buf = 0;
    }

    // epilogue: write partials (unique writer per element -> deterministic)
    int g = lane >> 2, q = lane & 3;
    size_t pbase = (size_t)(mt * SPLITS + sp) * MTILE * ND;
#pragma unroll
    for (int mi = 0; mi < 2; mi++)
#pragma unroll
        for (int nt = 0; nt < 2; nt++) {
            int lrow = wm * 32 + mi * 16 + g;
            int col = wn * 16 + nt * 8 + q * 2;
            float2* p0 = reinterpret_cast<float2*>(&g_part[pbase + (size_t)lrow * ND + col]);
            *p0 = make_float2(acc[mi][nt][0], acc[mi][nt][1]);
            float2* p1 = reinterpret_cast<float2*>(&g_part[pbase + (size_t)(lrow + 8) * ND + col]);
            *p1 = make_float2(acc[mi][nt][2], acc[mi][nt][3]);
        }
}

// ---------------- split-K reduce * invscale + bias (+x) + ReLU + amax ----------------
__global__ void k_reduce(int c, int L, int addX, int writeOut,
                         const float* __restrict__ x, float* __restrict__ dout) {
    __shared__ float smax[8];
    int t = threadIdx.x;
    int idx = blockIdx.x * 256 + t;   // a*64 + o
    int a = idx >> 6;
    int o = idx & 63;
    int mtl = a >> 7;
    int lr = a & 127;
    float inv = w_invscale(c, L);
    float s = 0.f;
#pragma unroll
    for (int sp = 0; sp < SPLITS; sp++)
        s += g_part[(size_t)(mtl * SPLITS + sp) * MTILE * ND + (size_t)lr * ND + o];
    float v = s * inv + g_bias[L][idx];
    if (addX) v += x[idx];
    v = fmaxf(v, 0.f);
    g_act[idx] = v;
    if (writeOut) dout[idx] = v;
    float mx = v;
#pragma unroll
    for (int off = 16; off; off >>= 1)
        mx = fmaxf(mx, __shfl_xor_sync(0xffffffffu, mx, off));
    if ((t & 31) == 0) smax[t >> 5] = mx;
    __syncthreads();
    if (t == 0) {
#pragma unroll
        for (int ww = 1; ww < 8; ww++) mx = fmaxf(mx, smax[ww]);
        atomicMax(&g_amax_bits[c + 1], __float_as_uint(mx));
    }
}

// ---------------- launcher ----------------
extern "C" void kernel_launch(void* const* d_in, const int* in_sizes, int n_in,
                              void* d_out, int out_size) {
    const float* x    = (const float*)d_in[0];   // (2048, 64)
    const float* conn = (const float*)d_in[1];   // (2048, 2048, 12)
    const float* bond = (const float*)d_in[2];   // (2048, 12, 2)
    const float* f0   = (const float*)d_in[3];   // (64, 12, 66)
    const float* f1   = (const float*)d_in[4];   // (64, 12, 66)
    float* out = (float*)d_out;                  // (2048, 64)

    cudaFuncSetAttribute(k_gemm, cudaFuncAttributeMaxDynamicSharedMemorySize, GEMM_SMEM);

    int n4 = (NA * NA * NF) / 4;                 // 12,582,912

    // Order: the 4th launch (index 3) is what ncu captures -> k_gemm (512-thread form).
    // Dependencies: prepB supplies Ft+scale for k_W; prepA(bias) only needed by reduce.
    k_conv_half<<<(n4 + 511) / 512, 256>>>((const float4*)conn, n4);  // 0
    k_prepB<<<387, 256>>>(x, f0, f1);                                 // 1
    k_W<<<dim3(64, 8), 256>>>(x, 0, 0);                               // 2 (c=0)
    k_gemm<<<dim3(NA / MTILE, SPLITS), GT, GEMM_SMEM>>>();            // 3 <- captured
    k_prepA<<<512, 256>>>(bond, f0, f1);                              // 4
    k_reduce<<<(NA * ND) / 256, 256>>>(0, 0, 0, 0, x, out);           // 5

    for (int c = 1; c < 4; c++) {
        int L = c >> 1;
        k_W<<<dim3(64, 8), 256>>>(x, c, L);
        k_gemm<<<dim3(NA / MTILE, SPLITS), GT, GEMM_SMEM>>>();
        k_reduce<<<(NA * ND) / 256, 256>>>(c, L, c & 1, (c == 3) ? 1 : 0, x, out);
    }
}

// round 16
// speedup vs baseline: 2.2897x; 1.0356x over previous
#include <cuda_runtime.h>
#include <cuda_fp16.h>
#include <cstdint>

// Problem constants
#define NA   2048           // atoms
#define ND   64             // depth
#define NF   12             // filters
#define KTOT (NA * NF)      // 24576, GEMM K
#define DP2  (ND + 2)       // 66
#define FSTR (NF * DP2)     // 792

// GEMM tiling
#define MTILE   128
#define SPLITS  8
#define KCHUNK  (KTOT / SPLITS)   // 3072
#define KB      64                // k per smem stage
#define NSTAGES (KCHUNK / KB)     // 48
#define SPAD    72                // row stride in halves (144B; ldmatrix conflict-free)
#define PIPE    4                 // cp.async pipeline depth
#define GEMM_SMEM (PIPE * (MTILE + ND) * SPAD * 2)   // 110592 B dynamic smem

// ---------------- device scratch (static module allocations, no runtime alloc) ---------
__device__ __align__(16) __half g_connH[(size_t)NA * KTOT];     // ~100.7 MB fp16 conn
__device__ __align__(16) __half g_WT[(size_t)ND * KTOT];        // W fp16 scaled [o][k]
__device__ __align__(16) float  g_Ft[2 * NF * ND * ND];         // filters transposed [L][f][d][o]
__device__ __align__(16) float  g_bias[2][NA * ND];
__device__ __align__(16) float  g_act[NA * ND];
__device__ __align__(16) float  g_part[(NA / MTILE) * SPLITS * MTILE * ND];
__device__ int g_ctr[NA / MTILE];                               // split-K arrival counters
__device__ unsigned int g_amax_bits[5];
__device__ float g_B[2];

// ---------------- helpers ----------------
__device__ __forceinline__ uint32_t smem_u32(const void* p) {
    return (uint32_t)__cvta_generic_to_shared(p);
}

__device__ __forceinline__ void ldmx4(uint32_t* r, uint32_t addr) {
    asm volatile("ldmatrix.sync.aligned.m8n8.x4.shared.b16 {%0,%1,%2,%3}, [%4];"
                 : "=r"(r[0]), "=r"(r[1]), "=r"(r[2]), "=r"(r[3]) : "r"(addr));
}

__device__ __forceinline__ void mma16816(float* c, const uint32_t* a, uint32_t b0, uint32_t b1) {
    asm volatile(
        "mma.sync.aligned.m16n8k16.row.col.f32.f16.f16.f32 "
        "{%0,%1,%2,%3}, {%4,%5,%6,%7}, {%8,%9}, {%0,%1,%2,%3};"
        : "+f"(c[0]), "+f"(c[1]), "+f"(c[2]), "+f"(c[3])
        : "r"(a[0]), "r"(a[1]), "r"(a[2]), "r"(a[3]), "r"(b0), "r"(b1));
}

// scale = 2^(14-e) if bound >= 2^14 else 1 (power of 2 -> exact)
__device__ __forceinline__ float w_scale(int c, int L) {
    float bound = __uint_as_float(g_amax_bits[c]) * g_B[L];
    int e; frexpf(bound, &e);
    return (e > 14) ? ldexpf(1.f, 14 - e) : 1.f;
}
__device__ __forceinline__ float w_invscale(int c, int L) {
    float bound = __uint_as_float(g_amax_bits[c]) * g_B[L];
    int e; frexpf(bound, &e);
    return (e > 14) ? ldexpf(1.f, e - 14) : 1.f;
}

// ---------------- kernel: fp32 conn -> fp16, 2 block-strided float4 per thread --------
__global__ void k_conv_half(const float4* __restrict__ src, int n4) {
    int base = blockIdx.x * 512 + threadIdx.x;
    uint2* dst = reinterpret_cast<uint2*>(g_connH);
#pragma unroll
    for (int j = 0; j < 2; j++) {
        int i = base + j * 256;
        if (i < n4) {
            float4 v = __ldcs(&src[i]);
            __half2 h0 = __floats2half2_rn(v.x, v.y);
            __half2 h1 = __floats2half2_rn(v.z, v.w);
            uint2 u;
            u.x = *reinterpret_cast<uint32_t*>(&h0);
            u.y = *reinterpret_cast<uint32_t*>(&h1);
            dst[i] = u;
        }
    }
}

// ---------------- fused prep: bounds + amax + counters + Ft transpose + bias ----------
// blocks 0,1 -> g_B[L]; 2 -> amax(x) + zero amax slots + zero ctr;
// 3..386 -> Ft transpose; 387..898 -> bias
__global__ void k_prep(const float* __restrict__ x, const float* __restrict__ bond,
                       const float* __restrict__ f0, const float* __restrict__ f1) {
    __shared__ float sred[256];
    int b = blockIdx.x;
    int t = threadIdx.x;
    if (b >= 387) {
        int i = (b - 387) * 256 + t;           // < 131072 = 2048*64
        int a = i >> 6, o = i & 63;
        float bb[NF * 2];
#pragma unroll
        for (int j = 0; j < NF * 2; j++) bb[j] = bond[a * NF * 2 + j];
#pragma unroll
        for (int L = 0; L < 2; L++) {
            const float* flt = L ? f1 : f0;
            float s = 0.f;
#pragma unroll
            for (int f = 0; f < NF; f++) {
                s += bb[f * 2 + 0] * flt[o * FSTR + f * DP2 + ND + 0];
                s += bb[f * 2 + 1] * flt[o * FSTR + f * DP2 + ND + 1];
            }
            g_bias[L][i] = s;
        }
        return;
    }
    if (b >= 3) {
        int idx = (b - 3) * 256 + t;           // < 98304 = 2*12*64*64
        int o = idx & 63;
        int d = (idx >> 6) & 63;
        int f = (idx >> 12) % NF;
        int L = idx / (NF * ND * ND);
        const float* src = L ? f1 : f0;
        g_Ft[idx] = src[o * FSTR + f * DP2 + d];
        return;
    }
    if (b < 2) {
        const float* flt = b ? f1 : f0;
        float mx = 0.f;
        for (int i = t; i < ND * NF; i += 256) {
            int o = i / NF, f = i - o * NF;
            const float* p = flt + o * FSTR + f * DP2;
            float s = 0.f;
#pragma unroll
            for (int d = 0; d < ND; d++) s += fabsf(p[d]);
            mx = fmaxf(mx, s);
        }
        sred[t] = mx;
        __syncthreads();
        for (int off = 128; off; off >>= 1) {
            if (t < off) sred[t] = fmaxf(sred[t], sred[t + off]);
            __syncthreads();
        }
        if (t == 0) g_B[b] = sred[0];
    } else {
        float mx = 0.f;
        for (int i = t; i < NA * ND; i += 256) mx = fmaxf(mx, fabsf(x[i]));
        sred[t] = mx;
        __syncthreads();
        for (int off = 128; off; off >>= 1) {
            if (t < off) sred[t] = fmaxf(sred[t], sred[t + off]);
            __syncthreads();
        }
        if (t == 0) {
            g_amax_bits[0] = __float_as_uint(sred[0]);
            g_amax_bits[1] = 0u; g_amax_bits[2] = 0u;
            g_amax_bits[3] = 0u; g_amax_bits[4] = 0u;
        }
        if (t < NA / MTILE) g_ctr[t] = 0;
    }
}

// ---------------- k_W v2: one thread = one atom row, 12 accumulators ------------------
// grid (64 o, 8 n-chunks), 256 threads; coalesced staged writes
__global__ void k_W(const float* __restrict__ xin, int c, int L) {
    __shared__ float sF[NF * ND];                 // Ft column for this o: [f][d]
    __shared__ __align__(16) __half sW[256 * NF]; // 6 KB staging
    int o = blockIdx.x;
    int t = threadIdx.x;
    const float* act = (c == 0) ? xin : g_act;
    float sc = w_scale(c, L);
    for (int i = t; i < NF * ND; i += 256)
        sF[i] = g_Ft[(L * NF * ND + i) * ND + o];
    __syncthreads();

    int n = blockIdx.y * 256 + t;
    float4 row[16];
    const float4* ar = reinterpret_cast<const float4*>(act + n * ND);
#pragma unroll
    for (int i = 0; i < 16; i++) row[i] = ar[i];

#pragma unroll
    for (int f = 0; f < NF; f++) {
        const float4* fr = reinterpret_cast<const float4*>(&sF[f * ND]);
        float s = 0.f;
#pragma unroll
        for (int i = 0; i < 16; i++) {
            float4 v = row[i];
            float4 wv = fr[i];
            s += v.x * wv.x + v.y * wv.y + v.z * wv.z + v.w * wv.w;
        }
        sW[t * NF + f] = __float2half_rn(s * sc);
    }
    __syncthreads();

    const uint32_t* sw32 = reinterpret_cast<const uint32_t*>(sW);
    uint32_t* dst = reinterpret_cast<uint32_t*>(
        g_WT + (size_t)o * KTOT + (size_t)blockIdx.y * (256 * NF));
#pragma unroll
    for (int i = 0; i < 6; i++)
        dst[i * 256 + t] = sw32[i * 256 + t];
}

// ---------------- split-K GEMM + fused reduce epilogue ----------------
// grid (16 m-tiles, 8 splits), 256 threads = 8 warps (4x2), warp tile 32x32.
// Last CTA per m-tile (atomic counter) performs the deterministic split-K
// reduction + bias (+x) + ReLU + amax, eliminating the separate reduce kernel.
__global__ __launch_bounds__(256, 1) void k_gemm(int c, int L, int addX, int writeOut,
                                                 const float* __restrict__ x,
                                                 float* __restrict__ dout) {
    extern __shared__ __align__(16) __half dyn[];
    __half* sAb = dyn;                          // [PIPE][MTILE][SPAD]
    __half* sBb = dyn + PIPE * MTILE * SPAD;    // [PIPE][ND][SPAD]

    int t = threadIdx.x;
    int mt = blockIdx.x, sp = blockIdx.y;
    int K0 = sp * KCHUNK;
    int lane = t & 31, w = t >> 5;
    int wm = w & 3, wn = w >> 2;

    float acc[2][4][4];
#pragma unroll
    for (int i = 0; i < 2; i++)
#pragma unroll
        for (int j = 0; j < 4; j++)
#pragma unroll
            for (int q = 0; q < 4; q++) acc[i][j][q] = 0.f;

    auto LOAD = [&](int buf, int kb) {
        __half* A = sAb + buf * MTILE * SPAD;
        __half* B = sBb + buf * ND * SPAD;
#pragma unroll
        for (int j = 0; j < 4; j++) {
            int idx = j * 256 + t;
            int row = idx >> 3, c16 = idx & 7;
            const __half* src = g_connH + (size_t)(mt * MTILE + row) * KTOT + K0 + kb + c16 * 8;
            uint32_t dst = smem_u32(A + row * SPAD + c16 * 8);
            asm volatile("cp.async.cg.shared.global [%0], [%1], 16;" :: "r"(dst), "l"(src));
        }
#pragma unroll
        for (int j = 0; j < 2; j++) {
            int idx = j * 256 + t;
            int row = idx >> 3, c16 = idx & 7;
            const __half* src = g_WT + (size_t)row * KTOT + K0 + kb + c16 * 8;
            uint32_t dst = smem_u32(B + row * SPAD + c16 * 8);
            asm volatile("cp.async.cg.shared.global [%0], [%1], 16;" :: "r"(dst), "l"(src));
        }
        asm volatile("cp.async.commit_group;");
    };

    int ar = (lane & 7) + ((lane >> 3) & 1) * 8;   // A-fragment row within m16
    int asel = (lane >> 4) * 8;                    // A-fragment k-half
    int br = (lane & 7) + (lane >> 4) * 8;         // B n-row select
    int bsel = ((lane >> 3) & 1) * 8;              // B k-half

    auto COMPUTE = [&](int buf) {
        __half* A = sAb + buf * MTILE * SPAD;
        __half* B = sBb + buf * ND * SPAD;
#pragma unroll
        for (int kk = 0; kk < KB; kk += 16) {
            uint32_t a[2][4], b[2][4];
#pragma unroll
            for (int mi = 0; mi < 2; mi++) {
                uint32_t ad = smem_u32(A + (wm * 32 + mi * 16 + ar) * SPAD + kk + asel);
                ldmx4(a[mi], ad);
            }
#pragma unroll
            for (int p = 0; p < 2; p++) {
                uint32_t bd = smem_u32(B + (wn * 32 + p * 16 + br) * SPAD + kk + bsel);
                ldmx4(b[p], bd);
            }
#pragma unroll
            for (int mi = 0; mi < 2; mi++)
#pragma unroll
                for (int nt = 0; nt < 4; nt++)
                    mma16816(acc[mi][nt], a[mi], b[nt >> 1][(nt & 1) * 2], b[nt >> 1][(nt & 1) * 2 + 1]);
        }
    };

#pragma unroll
    for (int s = 0; s < PIPE - 1; s++) LOAD(s, s * KB);

    int buf = 0;
    for (int s = 0; s < NSTAGES; s++) {
        asm volatile("cp.async.wait_group %0;" :: "n"(PIPE - 2));
        __syncthreads();
        int nxt = s + PIPE - 1;
        if (nxt < NSTAGES) {
            int wb = buf + (PIPE - 1); if (wb >= PIPE) wb -= PIPE;
            LOAD(wb, nxt * KB);
        } else {
            asm volatile("cp.async.commit_group;");
        }
        COMPUTE(buf);
        if (++buf == PIPE) buf = 0;
    }

    // write partials (unique writer per element -> deterministic)
    int g = lane >> 2, q = lane & 3;
    size_t pbase = (size_t)(mt * SPLITS + sp) * MTILE * ND;
#pragma unroll
    for (int mi = 0; mi < 2; mi++)
#pragma unroll
        for (int nt = 0; nt < 4; nt++) {
            int lrow = wm * 32 + mi * 16 + g;
            int col = wn * 32 + nt * 8 + q * 2;
            float2* p0 = reinterpret_cast<float2*>(&g_part[pbase + (size_t)lrow * ND + col]);
            *p0 = make_float2(acc[mi][nt][0], acc[mi][nt][1]);
            float2* p1 = reinterpret_cast<float2*>(&g_part[pbase + (size_t)(lrow + 8) * ND + col]);
            *p1 = make_float2(acc[mi][nt][2], acc[mi][nt][3]);
        }

    // ---- fused split-K reduce: last CTA per m-tile does it ----
    __threadfence();
    __shared__ int s_last;
    __shared__ float smax[8];
    if (t == 0) {
        int old = atomicAdd(&g_ctr[mt], 1);
        s_last = (old == SPLITS - 1);
    }
    __syncthreads();
    if (!s_last) return;
    __threadfence();   // acquire: make all CTAs' partial writes visible

    float inv = w_invscale(c, L);
    float mx = 0.f;
    size_t tile0 = (size_t)mt * SPLITS * MTILE * ND;
    int gbase = mt * MTILE * ND;
    // 8192 floats = 2048 float4; 256 threads x 8 float4
#pragma unroll
    for (int it = 0; it < 8; it++) {
        int i = it * 256 + t;            // float4 index within tile
        float4 s = make_float4(0.f, 0.f, 0.f, 0.f);
#pragma unroll
        for (int sp2 = 0; sp2 < SPLITS; sp2++) {
            float4 v = *(reinterpret_cast<const float4*>(&g_part[tile0 + (size_t)sp2 * MTILE * ND]) + i);
            s.x += v.x; s.y += v.y; s.z += v.z; s.w += v.w;
        }
        int gidx = gbase + i * 4;        // a*64 + o linear
        float4 b4 = *reinterpret_cast<const float4*>(&g_bias[L][gidx]);
        float4 r;
        r.x = s.x * inv + b4.x;
        r.y = s.y * inv + b4.y;
        r.z = s.z * inv + b4.z;
        r.w = s.w * inv + b4.w;
        if (addX) {
            float4 xv = *reinterpret_cast<const float4*>(&x[gidx]);
            r.x += xv.x; r.y += xv.y; r.z += xv.z; r.w += xv.w;
        }
        r.x = fmaxf(r.x, 0.f); r.y = fmaxf(r.y, 0.f);
        r.z = fmaxf(r.z, 0.f); r.w = fmaxf(r.w, 0.f);
        *reinterpret_cast<float4*>(&g_act[gidx]) = r;
        if (writeOut) *reinterpret_cast<float4*>(&dout[gidx]) = r;
        mx = fmaxf(mx, fmaxf(fmaxf(r.x, r.y), fmaxf(r.z, r.w)));
    }
#pragma unroll
    for (int off = 16; off; off >>= 1)
        mx = fmaxf(mx, __shfl_xor_sync(0xffffffffu, mx, off));
    if (lane == 0) smax[w] = mx;
    __syncthreads();
    if (t == 0) {
#pragma unroll
        for (int ww = 1; ww < 8; ww++) mx = fmaxf(mx, smax[ww]);
        atomicMax(&g_amax_bits[c + 1], __float_as_uint(mx));
        g_ctr[mt] = 0;   // reset for next gemm launch
    }
}

// ---------------- launcher ----------------
extern "C" void kernel_launch(void* const* d_in, const int* in_sizes, int n_in,
                              void* d_out, int out_size) {
    const float* x    = (const float*)d_in[0];   // (2048, 64)
    const float* conn = (const float*)d_in[1];   // (2048, 2048, 12)
    const float* bond = (const float*)d_in[2];   // (2048, 12, 2)
    const float* f0   = (const float*)d_in[3];   // (64, 12, 66)
    const float* f1   = (const float*)d_in[4];   // (64, 12, 66)
    float* out = (float*)d_out;                  // (2048, 64)

    cudaFuncSetAttribute(k_gemm, cudaFuncAttributeMaxDynamicSharedMemorySize, GEMM_SMEM);

    int n4 = (NA * NA * NF) / 4;                 // 12,582,912

    // Launch #4 (the ncu capture slot) = k_gemm(c=0) with the fused epilogue.
    k_conv_half<<<(n4 + 511) / 512, 256>>>((const float4*)conn, n4);  // 1
    k_prep<<<899, 256>>>(x, bond, f0, f1);                            // 2
    for (int c = 0; c < 4; c++) {
        int L = c >> 1;
        k_W<<<dim3(64, 8), 256>>>(x, c, L);
        k_gemm<<<dim3(NA / MTILE, SPLITS), 256, GEMM_SMEM>>>(
            c, L, c & 1, (c == 3) ? 1 : 0, x, out);
    }
}